// round 16
// baseline (speedup 1.0000x reference)
#include <cuda_runtime.h>
#include <cuda_fp16.h>
#include <cstdint>

#define S_LEN 2048
#define D_DIM 1024
#define BATCH 4
#define MTOT  (BATCH * S_LEN)   // 8192

// ---------------- scratch (static device arrays; allocation-guard safe) ----
__device__ __half g_xh[(size_t)MTOT * D_DIM];        // x split hi
__device__ __half g_xl[(size_t)MTOT * D_DIM];        // x split lo
__device__ __half g_wth[(size_t)3 * D_DIM * D_DIM];  // W^T split hi [3][e][d]
__device__ __half g_wtl[(size_t)3 * D_DIM * D_DIM];
__device__ __half g_qkh[(size_t)2 * MTOT * D_DIM];   // Q then K, split hi
__device__ __half g_qkl[(size_t)2 * MTOT * D_DIM];
__device__ __half g_vth[(size_t)BATCH * D_DIM * S_LEN]; // V^T split [4][e][s]
__device__ __half g_vtl[(size_t)BATCH * D_DIM * S_LEN];
__device__ float  g_scores[(size_t)BATCH * S_LEN * S_LEN];
__device__ __half g_ph[(size_t)BATCH * S_LEN * S_LEN];  // attn hi (lo not needed)

#define NPERS 296   // 148 SMs x 2 CTAs/SM — persistent grid size

// ---------------- helpers ---------------------------------------------------
__device__ __forceinline__ uint32_t smem_u32(const void* p) {
    uint32_t a;
    asm("{ .reg .u64 t; cvta.to.shared.u64 t, %1; cvt.u32.u64 %0, t; }"
        : "=r"(a) : "l"(p));
    return a;
}
__device__ __forceinline__ void cpa16(uint32_t saddr, const void* g) {
    asm volatile("cp.async.cg.shared.global [%0], [%1], 16;"
                 :: "r"(saddr), "l"(g));
}
__device__ __forceinline__ void cpa_commit() {
    asm volatile("cp.async.commit_group;");
}
template <int N>
__device__ __forceinline__ void cpa_wait() {
    asm volatile("cp.async.wait_group %0;" :: "n"(N));
}
__device__ __forceinline__ void ldmx4(uint32_t* d, uint32_t addr) {
    asm volatile("ldmatrix.sync.aligned.m8n8.x4.shared.b16 {%0,%1,%2,%3}, [%4];"
                 : "=r"(d[0]), "=r"(d[1]), "=r"(d[2]), "=r"(d[3]) : "r"(addr));
}
__device__ __forceinline__ void mma16816(float* c, const uint32_t* a,
                                         uint32_t b0, uint32_t b1) {
    asm volatile(
        "mma.sync.aligned.m16n8k16.row.col.f32.f16.f16.f32 "
        "{%0,%1,%2,%3}, {%4,%5,%6,%7}, {%8,%9}, {%0,%1,%2,%3};\n"
        : "+f"(c[0]), "+f"(c[1]), "+f"(c[2]), "+f"(c[3])
        : "r"(a[0]), "r"(a[1]), "r"(a[2]), "r"(a[3]), "r"(b0), "r"(b1));
}
// fp32 -> fp16 hi + fp16 residual-lo (captures ~22 mantissa bits total)
__device__ __forceinline__ void split4(float4 v, uint2& h, uint2& l) {
    __half2 h01 = __floats2half2_rn(v.x, v.y);
    __half2 h23 = __floats2half2_rn(v.z, v.w);
    __half2 l01 = __floats2half2_rn(v.x - __low2float(h01),
                                    v.y - __high2float(h01));
    __half2 l23 = __floats2half2_rn(v.z - __low2float(h23),
                                    v.w - __high2float(h23));
    h.x = *reinterpret_cast<uint32_t*>(&h01);
    h.y = *reinterpret_cast<uint32_t*>(&h23);
    l.x = *reinterpret_cast<uint32_t*>(&l01);
    l.y = *reinterpret_cast<uint32_t*>(&l23);
}

// ---------------- pre-processing kernels -----------------------------------
__global__ __launch_bounds__(256) void split_f32(const float* __restrict__ in,
                                                 __half* __restrict__ oh,
                                                 __half* __restrict__ ol) {
    size_t i = (size_t)blockIdx.x * 256 + threadIdx.x;
    float4 v = reinterpret_cast<const float4*>(in)[i];
    uint2 h, l; split4(v, h, l);
    reinterpret_cast<uint2*>(oh)[i] = h;
    reinterpret_cast<uint2*>(ol)[i] = l;
}

// transpose + split: fp32 [z][R][C] -> hi/lo fp16 [z][C][R]  (used for W only)
__global__ void transpose_split(const float* __restrict__ in,
                                __half* __restrict__ oh,
                                __half* __restrict__ ol,
                                int R, int C) {
    __shared__ float t[32][33];
    size_t boff = (size_t)blockIdx.z * R * C;
    in += boff; oh += boff; ol += boff;
    int c0 = blockIdx.x * 32, r0 = blockIdx.y * 32;
    int tx = threadIdx.x, ty = threadIdx.y;
    #pragma unroll
    for (int j = ty; j < 32; j += 8)
        t[j][tx] = in[(size_t)(r0 + j) * C + c0 + tx];
    __syncthreads();
    #pragma unroll
    for (int j = ty; j < 32; j += 8) {
        float v = t[tx][j];
        __half h = __float2half_rn(v);
        __half l = __float2half_rn(v - __half2float(h));
        size_t o = (size_t)(c0 + j) * R + r0 + tx;
        oh[o] = h; ol[o] = l;
    }
}

// ---------------------------------------------------------------------------
// Persistent fp16 hi/lo split GEMM: C = alpha * A * B^T   (A,B k-contiguous)
//   CTA 128x128, warps 4(M)x2(N) (warp tile 32x64), BK=32, 3-stage ring,
//   2 CTAs/SM, persistent tile loop (R14-proven config).
//   NTERMS=3: Ah*Bh + Ah*Bl + Al*Bh  (err ~2^-21)
//   NTERMS=2: Ah*Bh + Ah*Bl          (err ~2^-12 RMS; A-lo never loaded)
//   MODE 0: C fp32.   MODE 1: C written as fp16 hi/lo pair.
// ---------------------------------------------------------------------------
#define BM 128
#define BN 128
#define AH_OFF 0u
#define AL_OFF 8192u
#define BH_OFF 16384u
#define BL_OFF 24576u
#define STG_B  32768u
#define SMEM_BYTES (3 * 32768)   // 98304 per CTA -> 2 CTAs/SM

template <int MODE, int NTERMS>
__global__ __launch_bounds__(256, 2) void gemm_bs(
    const __half* __restrict__ Ah, const __half* __restrict__ Al,
    const __half* __restrict__ Bh, const __half* __restrict__ Bl,
    float* __restrict__ Cf, __half* __restrict__ Ch, __half* __restrict__ Cl,
    int N, int K, long sA, long sB, long sC, float alpha,
    int ntx, int nty, int ntz)
{
    extern __shared__ __align__(128) char smem[];
    const uint32_t sbase = smem_u32(smem);
    const int tid = threadIdx.x;
    const int lane = tid & 31, wid = tid >> 5;
    const int wm = wid >> 1, wn = wid & 1;   // 4(M) x 2(N)

    // ---- tile-invariant thread mappings ----
    const int arow = tid >> 2, ac = tid & 3;
    const uint32_t sOff = (uint32_t)arow * 64u
                        + (uint32_t)((ac ^ ((arow >> 1) & 3)) * 16);
    const int l15 = lane & 15, lh = lane >> 4;
    const int g8 = lane >> 3, r8 = lane & 7;
    const uint32_t aMsk = (uint32_t)((l15 >> 1) & 3);
    const uint32_t bMsk = (uint32_t)((r8 >> 1) & 3);
    uint32_t aBase[2], bBase[4];
    #pragma unroll
    for (int mi = 0; mi < 2; mi++)
        aBase[mi] = (uint32_t)(wm * 32 + mi * 16 + l15) * 64u;
    #pragma unroll
    for (int nj = 0; nj < 4; nj++)
        bBase[nj] = (uint32_t)(wn * 64 + nj * 16 + ((g8 >> 1) & 1) * 8 + r8) * 64u;

    const int nc = K >> 5;   // BK=32 chunks
    const int ntxy = ntx * nty;
    const int ntiles = ntxy * ntz;

    for (int t = blockIdx.x; t < ntiles; t += gridDim.x) {
        const int tz = t / ntxy;
        const int rr = t - tz * ntxy;
        const int tyi = rr / ntx;
        const int txi = rr - tyi * ntx;
        const long bm = (long)tyi * BM, bn = (long)txi * BN;

        const __half* gAh = Ah + (long)tz * sA + (bm + arow) * (long)K + ac * 8;
        const __half* gAl = Al + (long)tz * sA + (bm + arow) * (long)K + ac * 8;
        const __half* gBh = Bh + (long)tz * sB + (bn + arow) * (long)K + ac * 8;
        const __half* gBl = Bl + (long)tz * sB + (bn + arow) * (long)K + ac * 8;

        float acc[2][8][4];
        #pragma unroll
        for (int i = 0; i < 2; i++)
            #pragma unroll
            for (int j = 0; j < 8; j++)
                #pragma unroll
                for (int q = 0; q < 4; q++) acc[i][j][q] = 0.f;

        auto issue = [&](int kt, uint32_t stg) {
            uint32_t st = sbase + stg * STG_B;
            const __half* pah = gAh + (long)kt * 32;
            const __half* pal = gAl + (long)kt * 32;
            const __half* pbh = gBh + (long)kt * 32;
            const __half* pbl = gBl + (long)kt * 32;
            #pragma unroll
            for (int i = 0; i < 2; i++) {
                cpa16(st + AH_OFF + sOff + i * 4096u, pah + (long)(64 * i) * K);
                if (NTERMS == 3)
                    cpa16(st + AL_OFF + sOff + i * 4096u, pal + (long)(64 * i) * K);
                cpa16(st + BH_OFF + sOff + i * 4096u, pbh + (long)(64 * i) * K);
                cpa16(st + BL_OFF + sOff + i * 4096u, pbl + (long)(64 * i) * K);
            }
        };

        issue(0, 0); cpa_commit();
        issue(1, 1); cpa_commit();

        uint32_t stg = 0;                  // stage holding chunk kt
        for (int kt = 0; kt < nc; kt++) {
            cpa_wait<1>();                 // chunk kt landed
            __syncthreads();               // all warps done reading stage of kt-1

            const uint32_t stO = sbase + stg * STG_B;

            #pragma unroll
            for (int s = 0; s < 2; s++) {
                uint32_t ah[2][4], al[2][4];
                #pragma unroll
                for (int mi = 0; mi < 2; mi++) {
                    uint32_t phys = ((uint32_t)(2 * s + lh)) ^ aMsk;
                    uint32_t ad = stO + aBase[mi] + phys * 16u;
                    ldmx4(ah[mi], ad + AH_OFF);
                    if (NTERMS == 3) ldmx4(al[mi], ad + AL_OFF);
                }
                #pragma unroll
                for (int nj = 0; nj < 4; nj++) {
                    uint32_t phys = ((uint32_t)(2 * s + (g8 & 1))) ^ bMsk;
                    uint32_t bd = stO + bBase[nj] + phys * 16u;
                    uint32_t bh[4], bl[4];
                    ldmx4(bh, bd + BH_OFF);
                    ldmx4(bl, bd + BL_OFF);
                    // per-acc order hh,hl(,lh) fixed
                    mma16816(acc[0][2 * nj],     ah[0], bh[0], bh[1]);
                    mma16816(acc[1][2 * nj],     ah[1], bh[0], bh[1]);
                    mma16816(acc[0][2 * nj + 1], ah[0], bh[2], bh[3]);
                    mma16816(acc[1][2 * nj + 1], ah[1], bh[2], bh[3]);
                    mma16816(acc[0][2 * nj],     ah[0], bl[0], bl[1]);
                    mma16816(acc[1][2 * nj],     ah[1], bl[0], bl[1]);
                    mma16816(acc[0][2 * nj + 1], ah[0], bl[2], bl[3]);
                    mma16816(acc[1][2 * nj + 1], ah[1], bl[2], bl[3]);
                    if (NTERMS == 3) {
                        mma16816(acc[0][2 * nj],     al[0], bh[0], bh[1]);
                        mma16816(acc[1][2 * nj],     al[1], bh[0], bh[1]);
                        mma16816(acc[0][2 * nj + 1], al[0], bh[2], bh[3]);
                        mma16816(acc[1][2 * nj + 1], al[1], bh[2], bh[3]);
                    }
                }
                if (s == 0) {
                    if (kt + 2 < nc) {
                        uint32_t nstg = stg + 2; if (nstg >= 3) nstg -= 3;
                        issue(kt + 2, nstg);
                    }
                    cpa_commit();          // one commit per iteration (parity)
                }
            }
            if (++stg == 3) stg = 0;
        }

        // ---- epilogue ----
        #pragma unroll
        for (int mi = 0; mi < 2; mi++) {
            long r0 = bm + wm * 32 + mi * 16 + (lane >> 2);
            #pragma unroll
            for (int ni = 0; ni < 8; ni++) {
                long c = bn + wn * 64 + ni * 8 + 2 * (lane & 3);
                float v0 = alpha * acc[mi][ni][0], v1 = alpha * acc[mi][ni][1];
                float v2 = alpha * acc[mi][ni][2], v3 = alpha * acc[mi][ni][3];
                if (MODE == 0) {
                    float* Cb = Cf + (long)tz * sC;
                    *(float2*)(Cb + r0 * N + c)       = make_float2(v0, v1);
                    *(float2*)(Cb + (r0 + 8) * N + c) = make_float2(v2, v3);
                } else {
                    __half* Chb = Ch + (long)tz * sC;
                    __half* Clb = Cl + (long)tz * sC;
                    __half2 h0 = __floats2half2_rn(v0, v1);
                    __half2 l0 = __floats2half2_rn(v0 - __low2float(h0),
                                                   v1 - __high2float(h0));
                    __half2 h1 = __floats2half2_rn(v2, v3);
                    __half2 l1 = __floats2half2_rn(v2 - __low2float(h1),
                                                   v3 - __high2float(h1));
                    *(__half2*)(Chb + r0 * N + c)       = h0;
                    *(__half2*)(Clb + r0 * N + c)       = l0;
                    *(__half2*)(Chb + (r0 + 8) * N + c) = h1;
                    *(__half2*)(Clb + (r0 + 8) * N + c) = l1;
                }
            }
        }
        __syncthreads();   // protect smem stages before next tile overwrites
    }
}

// ---------------------------------------------------------------------------
// Row softmax over 2048 fp32 scores -> fp16 attn (hi only; out GEMM is
// 2-term and never reads the A-side lo plane). One CTA per row.
// ---------------------------------------------------------------------------
__global__ __launch_bounds__(256) void softmax_split(const float* __restrict__ S,
                                                     __half* __restrict__ Ph) {
    const float* row = S + (size_t)blockIdx.x * 2048;
    __half* ph = Ph + (size_t)blockIdx.x * 2048;
    const int tid = threadIdx.x;
    const int wid = tid >> 5, lane = tid & 31;
    __shared__ float smax[8], ssum[8];

    float4 va = reinterpret_cast<const float4*>(row)[2 * tid];
    float4 vb = reinterpret_cast<const float4*>(row)[2 * tid + 1];
    float v[8] = {va.x, va.y, va.z, va.w, vb.x, vb.y, vb.z, vb.w};

    float m = v[0];
    #pragma unroll
    for (int i = 1; i < 8; i++) m = fmaxf(m, v[i]);
    #pragma unroll
    for (int o = 16; o > 0; o >>= 1) m = fmaxf(m, __shfl_xor_sync(0xffffffffu, m, o));
    if (lane == 0) smax[wid] = m;
    __syncthreads();
    m = smax[0];
    #pragma unroll
    for (int w = 1; w < 8; w++) m = fmaxf(m, smax[w]);

    float s = 0.f;
    #pragma unroll
    for (int i = 0; i < 8; i++) { v[i] = __expf(v[i] - m); s += v[i]; }
    #pragma unroll
    for (int o = 16; o > 0; o >>= 1) s += __shfl_xor_sync(0xffffffffu, s, o);
    if (lane == 0) ssum[wid] = s;
    __syncthreads();
    s = 0.f;
    #pragma unroll
    for (int w = 0; w < 8; w++) s += ssum[w];

    float inv = 1.0f / s;
    uint32_t hp[4];
    #pragma unroll
    for (int i = 0; i < 4; i++) {
        __half2 h = __floats2half2_rn(v[2 * i] * inv, v[2 * i + 1] * inv);
        hp[i] = *reinterpret_cast<uint32_t*>(&h);
    }
    reinterpret_cast<uint4*>(ph)[tid] = make_uint4(hp[0], hp[1], hp[2], hp[3]);
}

// ---------------------------------------------------------------------------
// kernel_launch — multi-stream graph + persistent GEMMs (R14 schedule)
// ---------------------------------------------------------------------------
extern "C" void kernel_launch(void* const* d_in, const int* in_sizes, int n_in,
                              void* d_out, int out_size) {
    const float* x = (const float*)d_in[0];   // [4,2048,1024]
    const float* w = (const float*)d_in[1];   // [3,1024,1024]
    float* out = (float*)d_out;               // [4,2048,1024] fp32

    __half *xh, *xl, *wth, *wtl, *qkh, *qkl, *vth, *vtl, *ph;
    float *scores;
    cudaGetSymbolAddress((void**)&xh, g_xh);
    cudaGetSymbolAddress((void**)&xl, g_xl);
    cudaGetSymbolAddress((void**)&wth, g_wth);
    cudaGetSymbolAddress((void**)&wtl, g_wtl);
    cudaGetSymbolAddress((void**)&qkh, g_qkh);
    cudaGetSymbolAddress((void**)&qkl, g_qkl);
    cudaGetSymbolAddress((void**)&vth, g_vth);
    cudaGetSymbolAddress((void**)&vtl, g_vtl);
    cudaGetSymbolAddress((void**)&scores, g_scores);
    cudaGetSymbolAddress((void**)&ph, g_ph);

    static cudaStream_t sB = nullptr;
    static cudaEvent_t evFork, evX, evW, evQK, evVt, evBdone;
    if (!sB) {   // first call is the uncaptured correctness run
        cudaStreamCreateWithFlags(&sB, cudaStreamNonBlocking);
        cudaEventCreateWithFlags(&evFork,  cudaEventDisableTiming);
        cudaEventCreateWithFlags(&evX,     cudaEventDisableTiming);
        cudaEventCreateWithFlags(&evW,     cudaEventDisableTiming);
        cudaEventCreateWithFlags(&evQK,    cudaEventDisableTiming);
        cudaEventCreateWithFlags(&evVt,    cudaEventDisableTiming);
        cudaEventCreateWithFlags(&evBdone, cudaEventDisableTiming);
        cudaFuncSetAttribute(gemm_bs<1, 3>,
                             cudaFuncAttributeMaxDynamicSharedMemorySize, SMEM_BYTES);
        cudaFuncSetAttribute(gemm_bs<0, 2>,
                             cudaFuncAttributeMaxDynamicSharedMemorySize, SMEM_BYTES);
    }
    cudaStream_t s0 = 0;   // capture-origin (legacy) stream

    const long QH = 2048L * 1024;          // per-batch Q/K/out elements
    const long SC = 2048L * 2048;          // per-batch scores elements
    const long VT = 1024L * 2048;          // per-batch Vt elements

    // ---- fork sB off the capture stream ----
    cudaEventRecord(evFork, s0);
    cudaStreamWaitEvent(sB, evFork, 0);

    // s0: split x          sB: transpose+split W   (independent inputs)
    split_f32<<<8192, 256, 0, s0>>>(x, xh, xl);
    cudaEventRecord(evX, s0);
    transpose_split<<<dim3(32, 32, 3), dim3(32, 8), 0, sB>>>(w, wth, wtl, 1024, 1024);
    cudaEventRecord(evW, sB);

    // s0: QK GEMM (3-term)   tiles 8 x 64 x 2 = 1024
    cudaStreamWaitEvent(s0, evW, 0);
    gemm_bs<1, 3><<<NPERS, 256, SMEM_BYTES, s0>>>(
        xh, xl, wth, wtl, nullptr, qkh, qkl,
        1024, 1024, 0L, 1024L * 1024, 8192L * 1024, 1.0f,
        8, 64, 2);
    cudaEventRecord(evQK, s0);

    // sB: Vt GEMM (3-term)   tiles 16 x 8 x 4 = 512
    cudaStreamWaitEvent(sB, evX, 0);
    gemm_bs<1, 3><<<NPERS, 256, SMEM_BYTES, sB>>>(
        wth + 2L * 1024 * 1024, wtl + 2L * 1024 * 1024, xh, xl,
        nullptr, vth, vtl,
        2048, 1024, 0L, 2048L * 1024, 1024L * 2048, 1.0f,
        16, 8, 4);
    cudaEventRecord(evVt, sB);

    // ---- attention pipeline, batch halves {0,1} on s0 and {2,3} on sB ----
    // scores (2-term: Qh*Kh + Qh*Kl; Ql unused)
    gemm_bs<0, 2><<<NPERS, 256, SMEM_BYTES, s0>>>(
        qkh, qkl, qkh + 4 * QH, qkl + 4 * QH, scores, nullptr, nullptr,
        2048, 1024, QH, QH, SC, 0.03125f,
        16, 16, 2);
    softmax_split<<<4096, 256, 0, s0>>>(scores, ph);
    cudaStreamWaitEvent(s0, evVt, 0);
    // out (2-term: Ph*Vh + Ph*Vl; P-lo never materialized)
    gemm_bs<0, 2><<<NPERS, 256, SMEM_BYTES, s0>>>(
        ph, ph, vth, vtl, out, nullptr, nullptr,
        1024, 2048, SC, VT, QH, 1.0f,
        8, 16, 2);

    // sB half (batches 2,3)
    cudaStreamWaitEvent(sB, evQK, 0);
    gemm_bs<0, 2><<<NPERS, 256, SMEM_BYTES, sB>>>(
        qkh + 2 * QH, qkl + 2 * QH, qkh + 6 * QH, qkl + 6 * QH,
        scores + 2 * SC, nullptr, nullptr,
        2048, 1024, QH, QH, SC, 0.03125f,
        16, 16, 2);
    softmax_split<<<4096, 256, 0, sB>>>(scores + 2 * SC, ph + 2 * SC);
    gemm_bs<0, 2><<<NPERS, 256, SMEM_BYTES, sB>>>(
        ph + 2 * SC, ph + 2 * SC, vth + 2 * VT, vtl + 2 * VT, out + 2 * QH,
        nullptr, nullptr,
        1024, 2048, SC, VT, QH, 1.0f,
        8, 16, 2);
    cudaEventRecord(evBdone, sB);

    // ---- join back to capture stream ----
    cudaStreamWaitEvent(s0, evBdone, 0);
}

// round 17
// speedup vs baseline: 1.4095x; 1.4095x over previous
#include <cuda_runtime.h>
#include <cuda_bf16.h>
#include <cstdint>

#define S_LEN 2048
#define D_DIM 1024
#define BATCH 4
#define MTOT  (BATCH * S_LEN)   // 8192

// ---------------- scratch (static device arrays; allocation-guard safe) ----
__device__ __nv_bfloat16 g_xh[(size_t)MTOT * D_DIM];        // x split hi
__device__ __nv_bfloat16 g_xl[(size_t)MTOT * D_DIM];        // x split lo
__device__ __nv_bfloat16 g_wth[(size_t)3 * D_DIM * D_DIM];  // W^T split hi [3][e][d]
__device__ __nv_bfloat16 g_wtl[(size_t)3 * D_DIM * D_DIM];
__device__ __nv_bfloat16 g_qkh[(size_t)2 * MTOT * D_DIM];   // Q then K, split hi
__device__ __nv_bfloat16 g_qkl[(size_t)2 * MTOT * D_DIM];
__device__ __nv_bfloat16 g_vth[(size_t)BATCH * D_DIM * S_LEN]; // V^T split [4][e][s]
__device__ __nv_bfloat16 g_vtl[(size_t)BATCH * D_DIM * S_LEN];
__device__ float         g_scores[(size_t)BATCH * S_LEN * S_LEN];
__device__ __nv_bfloat16 g_ph[(size_t)BATCH * S_LEN * S_LEN];  // attn split
__device__ __nv_bfloat16 g_pl[(size_t)BATCH * S_LEN * S_LEN];

#define NPERS 296   // 148 SMs x 2 CTAs/SM — persistent grid size

// ---------------- helpers ---------------------------------------------------
__device__ __forceinline__ uint32_t smem_u32(const void* p) {
    uint32_t a;
    asm("{ .reg .u64 t; cvta.to.shared.u64 t, %1; cvt.u32.u64 %0, t; }"
        : "=r"(a) : "l"(p));
    return a;
}
__device__ __forceinline__ void cpa16(uint32_t saddr, const void* g) {
    asm volatile("cp.async.cg.shared.global [%0], [%1], 16;"
                 :: "r"(saddr), "l"(g));
}
__device__ __forceinline__ void cpa_commit() {
    asm volatile("cp.async.commit_group;");
}
template <int N>
__device__ __forceinline__ void cpa_wait() {
    asm volatile("cp.async.wait_group %0;" :: "n"(N));
}
__device__ __forceinline__ void ldmx4(uint32_t* d, uint32_t addr) {
    asm volatile("ldmatrix.sync.aligned.m8n8.x4.shared.b16 {%0,%1,%2,%3}, [%4];"
                 : "=r"(d[0]), "=r"(d[1]), "=r"(d[2]), "=r"(d[3]) : "r"(addr));
}
__device__ __forceinline__ void mma16816(float* c, const uint32_t* a,
                                         uint32_t b0, uint32_t b1) {
    asm volatile(
        "mma.sync.aligned.m16n8k16.row.col.f32.bf16.bf16.f32 "
        "{%0,%1,%2,%3}, {%4,%5,%6,%7}, {%8,%9}, {%0,%1,%2,%3};\n"
        : "+f"(c[0]), "+f"(c[1]), "+f"(c[2]), "+f"(c[3])
        : "r"(a[0]), "r"(a[1]), "r"(a[2]), "r"(a[3]), "r"(b0), "r"(b1));
}
__device__ __forceinline__ void split4(float4 v, uint2& h, uint2& l) {
    __nv_bfloat162 h01 = __floats2bfloat162_rn(v.x, v.y);
    __nv_bfloat162 h23 = __floats2bfloat162_rn(v.z, v.w);
    __nv_bfloat162 l01 = __floats2bfloat162_rn(v.x - __low2float(h01),
                                               v.y - __high2float(h01));
    __nv_bfloat162 l23 = __floats2bfloat162_rn(v.z - __low2float(h23),
                                               v.w - __high2float(h23));
    h.x = *reinterpret_cast<uint32_t*>(&h01);
    h.y = *reinterpret_cast<uint32_t*>(&h23);
    l.x = *reinterpret_cast<uint32_t*>(&l01);
    l.y = *reinterpret_cast<uint32_t*>(&l23);
}

// ---------------- pre-processing kernels -----------------------------------
__global__ __launch_bounds__(256) void split_f32(const float* __restrict__ in,
                                                 __nv_bfloat16* __restrict__ oh,
                                                 __nv_bfloat16* __restrict__ ol) {
    size_t i = (size_t)blockIdx.x * 256 + threadIdx.x;
    float4 v = reinterpret_cast<const float4*>(in)[i];
    uint2 h, l; split4(v, h, l);
    reinterpret_cast<uint2*>(oh)[i] = h;
    reinterpret_cast<uint2*>(ol)[i] = l;
}

// transpose + split: fp32 [z][R][C] -> hi/lo bf16 [z][C][R]  (used for W only)
__global__ void transpose_split(const float* __restrict__ in,
                                __nv_bfloat16* __restrict__ oh,
                                __nv_bfloat16* __restrict__ ol,
                                int R, int C) {
    __shared__ float t[32][33];
    size_t boff = (size_t)blockIdx.z * R * C;
    in += boff; oh += boff; ol += boff;
    int c0 = blockIdx.x * 32, r0 = blockIdx.y * 32;
    int tx = threadIdx.x, ty = threadIdx.y;
    #pragma unroll
    for (int j = ty; j < 32; j += 8)
        t[j][tx] = in[(size_t)(r0 + j) * C + c0 + tx];
    __syncthreads();
    #pragma unroll
    for (int j = ty; j < 32; j += 8) {
        float v = t[tx][j];
        __nv_bfloat16 h = __float2bfloat16(v);
        __nv_bfloat16 l = __float2bfloat16(v - __bfloat162float(h));
        size_t o = (size_t)(c0 + j) * R + r0 + tx;
        oh[o] = h; ol[o] = l;
    }
}

// ---------------------------------------------------------------------------
// Persistent bf16 hi/lo split GEMM: C = alpha * (Ah+Al)*(Bh+Bl)^T, 3 terms.
//   CTA 128x128, warps 4(M)x2(N), BK=32, 3-stage ring, 2 CTAs/SM,
//   persistent tile loop (R14-proven config, bit-identical results).
//   MODE 0: C fp32.   MODE 1: C written as bf16 hi/lo pair.
// ---------------------------------------------------------------------------
#define BM 128
#define BN 128
#define AH_OFF 0u
#define AL_OFF 8192u
#define BH_OFF 16384u
#define BL_OFF 24576u
#define STG_B  32768u
#define SMEM_BYTES (3 * 32768)   // 98304 per CTA -> 2 CTAs/SM

template <int MODE>
__global__ __launch_bounds__(256, 2) void gemm_bs(
    const __nv_bfloat16* __restrict__ Ah, const __nv_bfloat16* __restrict__ Al,
    const __nv_bfloat16* __restrict__ Bh, const __nv_bfloat16* __restrict__ Bl,
    float* __restrict__ Cf, __nv_bfloat16* __restrict__ Ch,
    __nv_bfloat16* __restrict__ Cl,
    int N, int K, long sA, long sB, long sC, float alpha,
    int ntx, int nty, int ntz)
{
    extern __shared__ __align__(128) char smem[];
    const uint32_t sbase = smem_u32(smem);
    const int tid = threadIdx.x;
    const int lane = tid & 31, wid = tid >> 5;
    const int wm = wid >> 1, wn = wid & 1;   // 4(M) x 2(N)

    const int arow = tid >> 2, ac = tid & 3;
    const uint32_t sOff = (uint32_t)arow * 64u
                        + (uint32_t)((ac ^ ((arow >> 1) & 3)) * 16);
    const int l15 = lane & 15, lh = lane >> 4;
    const int g8 = lane >> 3, r8 = lane & 7;
    const uint32_t aMsk = (uint32_t)((l15 >> 1) & 3);
    const uint32_t bMsk = (uint32_t)((r8 >> 1) & 3);
    uint32_t aBase[2], bBase[4];
    #pragma unroll
    for (int mi = 0; mi < 2; mi++)
        aBase[mi] = (uint32_t)(wm * 32 + mi * 16 + l15) * 64u;
    #pragma unroll
    for (int nj = 0; nj < 4; nj++)
        bBase[nj] = (uint32_t)(wn * 64 + nj * 16 + ((g8 >> 1) & 1) * 8 + r8) * 64u;

    const int nc = K >> 5;   // BK=32 chunks
    const int ntxy = ntx * nty;
    const int ntiles = ntxy * ntz;

    for (int t = blockIdx.x; t < ntiles; t += gridDim.x) {
        const int tz = t / ntxy;
        const int rr = t - tz * ntxy;
        const int tyi = rr / ntx;
        const int txi = rr - tyi * ntx;
        const long bm = (long)tyi * BM, bn = (long)txi * BN;

        const __nv_bfloat16* gAh = Ah + (long)tz * sA + (bm + arow) * (long)K + ac * 8;
        const __nv_bfloat16* gAl = Al + (long)tz * sA + (bm + arow) * (long)K + ac * 8;
        const __nv_bfloat16* gBh = Bh + (long)tz * sB + (bn + arow) * (long)K + ac * 8;
        const __nv_bfloat16* gBl = Bl + (long)tz * sB + (bn + arow) * (long)K + ac * 8;

        float acc[2][8][4];
        #pragma unroll
        for (int i = 0; i < 2; i++)
            #pragma unroll
            for (int j = 0; j < 8; j++)
                #pragma unroll
                for (int q = 0; q < 4; q++) acc[i][j][q] = 0.f;

        auto issue = [&](int kt, uint32_t stg) {
            uint32_t st = sbase + stg * STG_B;
            const __nv_bfloat16* pah = gAh + (long)kt * 32;
            const __nv_bfloat16* pal = gAl + (long)kt * 32;
            const __nv_bfloat16* pbh = gBh + (long)kt * 32;
            const __nv_bfloat16* pbl = gBl + (long)kt * 32;
            #pragma unroll
            for (int i = 0; i < 2; i++) {
                cpa16(st + AH_OFF + sOff + i * 4096u, pah + (long)(64 * i) * K);
                cpa16(st + AL_OFF + sOff + i * 4096u, pal + (long)(64 * i) * K);
                cpa16(st + BH_OFF + sOff + i * 4096u, pbh + (long)(64 * i) * K);
                cpa16(st + BL_OFF + sOff + i * 4096u, pbl + (long)(64 * i) * K);
            }
        };

        issue(0, 0); cpa_commit();
        issue(1, 1); cpa_commit();

        uint32_t stg = 0;                  // stage holding chunk kt
        for (int kt = 0; kt < nc; kt++) {
            cpa_wait<1>();                 // chunk kt landed
            __syncthreads();               // all warps done reading stage of kt-1

            const uint32_t stO = sbase + stg * STG_B;

            #pragma unroll
            for (int s = 0; s < 2; s++) {
                uint32_t ah[2][4], al[2][4];
                #pragma unroll
                for (int mi = 0; mi < 2; mi++) {
                    uint32_t phys = ((uint32_t)(2 * s + lh)) ^ aMsk;
                    uint32_t ad = stO + aBase[mi] + phys * 16u;
                    ldmx4(ah[mi], ad + AH_OFF);
                    ldmx4(al[mi], ad + AL_OFF);
                }
                #pragma unroll
                for (int nj = 0; nj < 4; nj++) {
                    uint32_t phys = ((uint32_t)(2 * s + (g8 & 1))) ^ bMsk;
                    uint32_t bd = stO + bBase[nj] + phys * 16u;
                    uint32_t bh[4], bl[4];
                    ldmx4(bh, bd + BH_OFF);
                    ldmx4(bl, bd + BL_OFF);
                    // per-acc order hh,hl,lh -> bit-identical accumulation
                    mma16816(acc[0][2 * nj],     ah[0], bh[0], bh[1]);
                    mma16816(acc[1][2 * nj],     ah[1], bh[0], bh[1]);
                    mma16816(acc[0][2 * nj + 1], ah[0], bh[2], bh[3]);
                    mma16816(acc[1][2 * nj + 1], ah[1], bh[2], bh[3]);
                    mma16816(acc[0][2 * nj],     ah[0], bl[0], bl[1]);
                    mma16816(acc[1][2 * nj],     ah[1], bl[0], bl[1]);
                    mma16816(acc[0][2 * nj + 1], ah[0], bl[2], bl[3]);
                    mma16816(acc[1][2 * nj + 1], ah[1], bl[2], bl[3]);
                    mma16816(acc[0][2 * nj],     al[0], bh[0], bh[1]);
                    mma16816(acc[1][2 * nj],     al[1], bh[0], bh[1]);
                    mma16816(acc[0][2 * nj + 1], al[0], bh[2], bh[3]);
                    mma16816(acc[1][2 * nj + 1], al[1], bh[2], bh[3]);
                }
                if (s == 0) {
                    if (kt + 2 < nc) {
                        uint32_t nstg = stg + 2; if (nstg >= 3) nstg -= 3;
                        issue(kt + 2, nstg);
                    }
                    cpa_commit();          // one commit per iteration (parity)
                }
            }
            if (++stg == 3) stg = 0;
        }

        // ---- epilogue ----
        #pragma unroll
        for (int mi = 0; mi < 2; mi++) {
            long r0 = bm + wm * 32 + mi * 16 + (lane >> 2);
            #pragma unroll
            for (int ni = 0; ni < 8; ni++) {
                long c = bn + wn * 64 + ni * 8 + 2 * (lane & 3);
                float v0 = alpha * acc[mi][ni][0], v1 = alpha * acc[mi][ni][1];
                float v2 = alpha * acc[mi][ni][2], v3 = alpha * acc[mi][ni][3];
                if (MODE == 0) {
                    float* Cb = Cf + (long)tz * sC;
                    *(float2*)(Cb + r0 * N + c)       = make_float2(v0, v1);
                    *(float2*)(Cb + (r0 + 8) * N + c) = make_float2(v2, v3);
                } else {
                    __nv_bfloat16* Chb = Ch + (long)tz * sC;
                    __nv_bfloat16* Clb = Cl + (long)tz * sC;
                    __nv_bfloat162 h0 = __floats2bfloat162_rn(v0, v1);
                    __nv_bfloat162 l0 = __floats2bfloat162_rn(v0 - __low2float(h0),
                                                              v1 - __high2float(h0));
                    __nv_bfloat162 h1 = __floats2bfloat162_rn(v2, v3);
                    __nv_bfloat162 l1 = __floats2bfloat162_rn(v2 - __low2float(h1),
                                                              v3 - __high2float(h1));
                    *(__nv_bfloat162*)(Chb + r0 * N + c)       = h0;
                    *(__nv_bfloat162*)(Clb + r0 * N + c)       = l0;
                    *(__nv_bfloat162*)(Chb + (r0 + 8) * N + c) = h1;
                    *(__nv_bfloat162*)(Clb + (r0 + 8) * N + c) = l1;
                }
            }
        }
        __syncthreads();   // protect smem stages before next tile overwrites
    }
}

// ---------------------------------------------------------------------------
// Row softmax over 2048 fp32 scores -> bf16 hi/lo attn. One CTA per row.
// ---------------------------------------------------------------------------
__global__ __launch_bounds__(256) void softmax_split(const float* __restrict__ S,
                                                     __nv_bfloat16* __restrict__ Ph,
                                                     __nv_bfloat16* __restrict__ Pl) {
    const float* row = S + (size_t)blockIdx.x * 2048;
    __nv_bfloat16* ph = Ph + (size_t)blockIdx.x * 2048;
    __nv_bfloat16* pl = Pl + (size_t)blockIdx.x * 2048;
    const int tid = threadIdx.x;
    const int wid = tid >> 5, lane = tid & 31;
    __shared__ float smax[8], ssum[8];

    float4 va = reinterpret_cast<const float4*>(row)[2 * tid];
    float4 vb = reinterpret_cast<const float4*>(row)[2 * tid + 1];
    float v[8] = {va.x, va.y, va.z, va.w, vb.x, vb.y, vb.z, vb.w};

    float m = v[0];
    #pragma unroll
    for (int i = 1; i < 8; i++) m = fmaxf(m, v[i]);
    #pragma unroll
    for (int o = 16; o > 0; o >>= 1) m = fmaxf(m, __shfl_xor_sync(0xffffffffu, m, o));
    if (lane == 0) smax[wid] = m;
    __syncthreads();
    m = smax[0];
    #pragma unroll
    for (int w = 1; w < 8; w++) m = fmaxf(m, smax[w]);

    float s = 0.f;
    #pragma unroll
    for (int i = 0; i < 8; i++) { v[i] = __expf(v[i] - m); s += v[i]; }
    #pragma unroll
    for (int o = 16; o > 0; o >>= 1) s += __shfl_xor_sync(0xffffffffu, s, o);
    if (lane == 0) ssum[wid] = s;
    __syncthreads();
    s = 0.f;
    #pragma unroll
    for (int w = 0; w < 8; w++) s += ssum[w];

    float inv = 1.0f / s;
    uint32_t hp[4], lp[4];
    #pragma unroll
    for (int i = 0; i < 4; i++) {
        float p0 = v[2 * i] * inv, p1 = v[2 * i + 1] * inv;
        __nv_bfloat162 h = __floats2bfloat162_rn(p0, p1);
        __nv_bfloat162 l = __floats2bfloat162_rn(p0 - __low2float(h),
                                                 p1 - __high2float(h));
        hp[i] = *reinterpret_cast<uint32_t*>(&h);
        lp[i] = *reinterpret_cast<uint32_t*>(&l);
    }
    reinterpret_cast<uint4*>(ph)[tid] = make_uint4(hp[0], hp[1], hp[2], hp[3]);
    reinterpret_cast<uint4*>(pl)[tid] = make_uint4(lp[0], lp[1], lp[2], lp[3]);
}

// ---------------------------------------------------------------------------
// kernel_launch — two symmetric batch-half chains; QK split by batch-half so
// scores can start at half-QK completion. All GEMMs are the R14 bf16 3-term
// persistent kernels (bit-identical math).
//   s0: splitX, QK[b01], scores[b01], softmax[b01], (wait Vt) out[b01]
//   sB: transW, Vt(all), QK[b23], scores[b23], softmax[b23], out[b23]
// ---------------------------------------------------------------------------
extern "C" void kernel_launch(void* const* d_in, const int* in_sizes, int n_in,
                              void* d_out, int out_size) {
    const float* x = (const float*)d_in[0];   // [4,2048,1024]
    const float* w = (const float*)d_in[1];   // [3,1024,1024]
    float* out = (float*)d_out;               // [4,2048,1024] fp32

    __nv_bfloat16 *xh, *xl, *wth, *wtl, *qkh, *qkl, *vth, *vtl, *ph, *pl;
    float *scores;
    cudaGetSymbolAddress((void**)&xh, g_xh);
    cudaGetSymbolAddress((void**)&xl, g_xl);
    cudaGetSymbolAddress((void**)&wth, g_wth);
    cudaGetSymbolAddress((void**)&wtl, g_wtl);
    cudaGetSymbolAddress((void**)&qkh, g_qkh);
    cudaGetSymbolAddress((void**)&qkl, g_qkl);
    cudaGetSymbolAddress((void**)&vth, g_vth);
    cudaGetSymbolAddress((void**)&vtl, g_vtl);
    cudaGetSymbolAddress((void**)&scores, g_scores);
    cudaGetSymbolAddress((void**)&ph, g_ph);
    cudaGetSymbolAddress((void**)&pl, g_pl);

    static cudaStream_t sB = nullptr;
    static cudaEvent_t evFork, evX, evW, evVt, evBdone;
    if (!sB) {   // first call is the uncaptured correctness run
        cudaStreamCreateWithFlags(&sB, cudaStreamNonBlocking);
        cudaEventCreateWithFlags(&evFork,  cudaEventDisableTiming);
        cudaEventCreateWithFlags(&evX,     cudaEventDisableTiming);
        cudaEventCreateWithFlags(&evW,     cudaEventDisableTiming);
        cudaEventCreateWithFlags(&evVt,    cudaEventDisableTiming);
        cudaEventCreateWithFlags(&evBdone, cudaEventDisableTiming);
        cudaFuncSetAttribute(gemm_bs<0>, cudaFuncAttributeMaxDynamicSharedMemorySize,
                             SMEM_BYTES);
        cudaFuncSetAttribute(gemm_bs<1>, cudaFuncAttributeMaxDynamicSharedMemorySize,
                             SMEM_BYTES);
    }
    cudaStream_t s0 = 0;   // capture-origin (legacy) stream

    const long QH = 2048L * 1024;          // per-batch Q/K/out elements
    const long SC = 2048L * 2048;          // per-batch scores elements
    const long VT = 1024L * 2048;          // per-batch Vt elements
    const long HM = 2L * QH;               // batch-half row block (4096 x 1024)

    // ---- fork sB off the capture stream ----
    cudaEventRecord(evFork, s0);
    cudaStreamWaitEvent(sB, evFork, 0);

    // s0: split x          sB: transpose+split W   (independent inputs)
    split_f32<<<8192, 256, 0, s0>>>(x, xh, xl);
    cudaEventRecord(evX, s0);
    transpose_split<<<dim3(32, 32, 3), dim3(32, 8), 0, sB>>>(w, wth, wtl, 1024, 1024);
    cudaEventRecord(evW, sB);

    // ---- s0 chain: QK for batches 0,1 (rows 0..4095), tiles 8x32x2 = 512 --
    cudaStreamWaitEvent(s0, evW, 0);
    gemm_bs<1><<<NPERS, 256, SMEM_BYTES, s0>>>(
        xh, xl, wth, wtl, nullptr, qkh, qkl,
        1024, 1024, 0L, 1024L * 1024, 8192L * 1024, 1.0f,
        8, 32, 2);

    // ---- sB chain: Vt (all 4 batches), tiles 16x8x4 = 512 -----------------
    cudaStreamWaitEvent(sB, evX, 0);
    gemm_bs<1><<<NPERS, 256, SMEM_BYTES, sB>>>(
        wth + 2L * 1024 * 1024, wtl + 2L * 1024 * 1024, xh, xl,
        nullptr, vth, vtl,
        2048, 1024, 0L, 2048L * 1024, 1024L * 2048, 1.0f,
        16, 8, 4);
    cudaEventRecord(evVt, sB);

    // sB: QK for batches 2,3 (rows 4096..8191)
    gemm_bs<1><<<NPERS, 256, SMEM_BYTES, sB>>>(
        xh + HM, xl + HM, wth, wtl, nullptr, qkh + HM, qkl + HM,
        1024, 1024, 0L, 1024L * 1024, 8192L * 1024, 1.0f,
        8, 32, 2);

    // ---- attention, batch halves {0,1} on s0 and {2,3} on sB --------------
    // s0: scores[b01]  tiles 16x16x2 = 512
    gemm_bs<0><<<NPERS, 256, SMEM_BYTES, s0>>>(
        qkh, qkl, qkh + 4 * QH, qkl + 4 * QH, scores, nullptr, nullptr,
        2048, 1024, QH, QH, SC, 0.03125f,
        16, 16, 2);
    softmax_split<<<4096, 256, 0, s0>>>(scores, ph, pl);
    cudaStreamWaitEvent(s0, evVt, 0);
    gemm_bs<0><<<NPERS, 256, SMEM_BYTES, s0>>>(
        ph, pl, vth, vtl, out, nullptr, nullptr,
        1024, 2048, SC, VT, QH, 1.0f,
        8, 16, 2);

    // sB: scores[b23] (Q rows b23 at qkh+HM; K rows b23 at qkh+4QH+HM)
    gemm_bs<0><<<NPERS, 256, SMEM_BYTES, sB>>>(
        qkh + HM, qkl + HM, qkh + 4 * QH + HM, qkl + 4 * QH + HM,
        scores + 2 * SC, nullptr, nullptr,
        2048, 1024, QH, QH, SC, 0.03125f,
        16, 16, 2);
    softmax_split<<<4096, 256, 0, sB>>>(scores + 2 * SC, ph + 2 * SC, pl + 2 * SC);
    gemm_bs<0><<<NPERS, 256, SMEM_BYTES, sB>>>(
        ph + 2 * SC, pl + 2 * SC, vth + 2 * VT, vtl + 2 * VT, out + 2 * QH,
        nullptr, nullptr,
        1024, 2048, SC, VT, QH, 1.0f,
        8, 16, 2);
    cudaEventRecord(evBdone, sB);

    // ---- join back to capture stream ----
    cudaStreamWaitEvent(s0, evBdone, 0);
}